// round 9
// baseline (speedup 1.0000x reference)
#include <cuda_runtime.h>

#define NB   512
#define NC   16
#define NT   2000
#define NRES 1024
#define NCLS 10
#define NBLK 148
#define ALPHA 0.9f

// Persistent cross-CTA state.
__device__ float g_s [2][NB * NRES];   // spikes, [b][j] (classifier layout)
__device__ float g_sT[2][NRES * NB];   // spikes, [j][b] (GEMM A layout)
__device__ float g_WresT[NRES * NRES]; // Wres^T, [k][j]
__device__ unsigned g_bar_count;
__device__ unsigned g_bar_gen;

static __device__ __forceinline__ unsigned ld_acq(const unsigned* p) {
    unsigned v;
    asm volatile("ld.acquire.gpu.global.u32 %0, [%1];" : "=r"(v) : "l"(p) : "memory");
    return v;
}
static __device__ __forceinline__ void st_rel(unsigned* p, unsigned v) {
    asm volatile("st.release.gpu.global.u32 [%0], %1;" :: "l"(p), "r"(v) : "memory");
}

// Grid-wide barrier; all 148 CTAs resident (1 per SM).
static __device__ __forceinline__ void grid_barrier() {
    __syncthreads();
    if (threadIdx.x == 0) {
        unsigned gen = ld_acq(&g_bar_gen);
        __threadfence();
        if (atomicAdd(&g_bar_count, 1u) == NBLK - 1u) {
            g_bar_count = 0u;
            __threadfence();
            st_rel(&g_bar_gen, gen + 1u);
        } else {
            while (ld_acq(&g_bar_gen) == gen) { }
        }
    }
    __syncthreads();
}

// fma.rn.f32x2: two independent rn fp32 FMAs — per-lane bit-identical.
static __device__ __forceinline__ unsigned long long pack2(float lo, float hi) {
    unsigned long long r;
    asm("mov.b64 %0, {%1, %2};" : "=l"(r) : "f"(lo), "f"(hi));
    return r;
}
static __device__ __forceinline__ void unpack2(unsigned long long p, float& lo, float& hi) {
    asm("mov.b64 {%0, %1}, %2;" : "=f"(lo), "=f"(hi) : "l"(p));
}
static __device__ __forceinline__ void fma2(unsigned long long& acc,
                                            unsigned long long a,
                                            unsigned long long b) {
    asm("fma.rn.f32x2 %0, %1, %2, %0;" : "+l"(acc) : "l"(a), "l"(b));
}

__global__ __launch_bounds__(256, 1) void reservoir_persistent(
    const float* __restrict__ x,     // (NB, NC, NT)
    const float* __restrict__ Win,   // (NRES, NC)
    const float* __restrict__ Wres,  // (NRES, NRES)
    const float* __restrict__ Wclf,  // (NCLS, NRES)
    float* __restrict__ out)         // [NB*NCLS | NB*NRES]
{
    const int blk = blockIdx.x;
    const int tid = threadIdx.x;

    // Pool: As = rows 0..31, Bs = rows 32..63 (each [32][68]);
    // aliased in the epilogue as spt[64][68] (spike transpose staging).
    __shared__ __align__(16) float pool[64 * 68];
    __shared__ float sx[64][17];
    __shared__ float sWin[64][17];
    float* const As = pool;             // As[k][bl] : k*68 + bl
    float* const Bs = pool + 32 * 68;   // Bs[k][jl] : k*68 + jl

    // ---- Phase 0 (all CTAs): transpose Wres once per launch ----
    {
        const int g0 = blk * 256 + tid;
        const int gs = NBLK * 256;
        for (int i = g0; i < NRES * NRES; i += gs) {
            int j = i >> 10, k = i & (NRES - 1);
            g_WresT[k * NRES + j] = Wres[i];
        }
    }

    if (blk < 128) {
        // ---------------- Reservoir path ----------------
        const int b0 = (blk >> 4) * 64;
        const int j0 = (blk & 15) * 64;
        const int ty = tid >> 4;          // row group 0..15
        const int tx = tid & 15;          // col group 0..15
        const int kl0 = tid >> 4;         // staging row (chunk half 0)
        const int qq  = tid & 15;         // staging quad

        // Zero step-0 spikes (both layouts).
        {
            float4 z = make_float4(0.f, 0.f, 0.f, 0.f);
#pragma unroll
            for (int i = 0; i < 4; i++)
                __stcg((float4*)&g_s[0][(size_t)(b0 + ty * 4 + i) * NRES + j0 + tx * 4], z);
            for (int e = tid; e < 64 * 16; e += 256) {
                int jl = e >> 4, bq = e & 15;
                __stcg((float4*)&g_sT[0][(size_t)(j0 + jl) * NB + b0 + bq * 4], z);
            }
        }
        for (int e = tid; e < 64 * 16; e += 256) {
            int r = e >> 4, c = e & 15;
            sWin[r][c] = Win[(size_t)(j0 + r) * NC + c];
        }

        float v[16], cnt[16];
#pragma unroll
        for (int q = 0; q < 16; q++) { v[q] = 0.f; cnt[q] = 0.f; }

        grid_barrier();

        for (int t = 0; t < NT; ++t) {
            const float* __restrict__ sTprev = g_sT[t & 1];
            float* __restrict__ s_next  = g_s [(t + 1) & 1];
            float* __restrict__ sT_next = g_sT[(t + 1) & 1];

            // Stage x_t tile (consumed in epilogue; covered by chunk syncs).
            for (int e = tid; e < 64 * 16; e += 256) {
                int r = e >> 4, c = e & 15;
                sx[r][c] = x[((size_t)(b0 + r) * NC + c) * NT + t];
            }

            // Frozen chain: single accumulator per output, k strictly
            // descending 1023..0; FFMA2 pairing identical to round 8.
            unsigned long long acc2[4][2];
#pragma unroll
            for (int i = 0; i < 4; i++) {
                acc2[i][0] = pack2(0.f, 0.f);
                acc2[i][1] = pack2(0.f, 0.f);
            }

            // Prefetch chunk 31 (k = 992..1023), fully coalesced.
            float4 pa0, pa1, pb0, pb1;
            {
                const int kg = 31 * 32;
                pa0 = __ldcg((const float4*)&sTprev[(size_t)(kg + kl0)      * NB + b0 + qq * 4]);
                pa1 = __ldcg((const float4*)&sTprev[(size_t)(kg + kl0 + 16) * NB + b0 + qq * 4]);
                pb0 = __ldg ((const float4*)&g_WresT[(size_t)(kg + kl0)      * NRES + j0 + qq * 4]);
                pb1 = __ldg ((const float4*)&g_WresT[(size_t)(kg + kl0 + 16) * NRES + j0 + qq * 4]);
            }

            for (int kc = 31; kc >= 0; --kc) {
                __syncthreads();   // prior compute done before overwrite
                *(float4*)&As[(kl0)      * 68 + qq * 4] = pa0;
                *(float4*)&As[(kl0 + 16) * 68 + qq * 4] = pa1;
                *(float4*)&Bs[(kl0)      * 68 + qq * 4] = pb0;
                *(float4*)&Bs[(kl0 + 16) * 68 + qq * 4] = pb1;
                __syncthreads();
                if (kc > 0) {
                    const int kg = (kc - 1) * 32;
                    pa0 = __ldcg((const float4*)&sTprev[(size_t)(kg + kl0)      * NB + b0 + qq * 4]);
                    pa1 = __ldcg((const float4*)&sTprev[(size_t)(kg + kl0 + 16) * NB + b0 + qq * 4]);
                    pb0 = __ldg ((const float4*)&g_WresT[(size_t)(kg + kl0)      * NRES + j0 + qq * 4]);
                    pb1 = __ldg ((const float4*)&g_WresT[(size_t)(kg + kl0 + 16) * NRES + j0 + qq * 4]);
                }
#pragma unroll
                for (int k = 31; k >= 0; --k) {
                    float4 a4 = *(const float4*)&As[k * 68 + ty * 4];
                    float4 b4 = *(const float4*)&Bs[k * 68 + tx * 4];
                    unsigned long long b01 = pack2(b4.x, b4.y);
                    unsigned long long b23 = pack2(b4.z, b4.w);
                    float aa[4] = {a4.x, a4.y, a4.z, a4.w};
#pragma unroll
                    for (int i = 0; i < 4; i++) {
                        unsigned long long ai2 = pack2(aa[i], aa[i]);
                        fma2(acc2[i][0], ai2, b01);
                        fma2(acc2[i][1], ai2, b23);
                    }
                }
            }

            float acc[4][4];
#pragma unroll
            for (int i = 0; i < 4; i++) {
                unpack2(acc2[i][0], acc[i][0], acc[i][1]);
                unpack2(acc2[i][1], acc[i][2], acc[i][3]);
            }

            __syncthreads();   // mainloop smem reads done; pool reused as spt

            // Epilogue (frozen): vn = rn(fma(0.9, v, d_in) + d_rec)
            float (*spt)[68] = (float(*)[68])pool;   // [jl][bl]
#pragma unroll
            for (int i = 0; i < 4; i++) {
                const int rb = ty * 4 + i;
                float sp[4];
#pragma unroll
                for (int j = 0; j < 4; j++) {
                    const int cj = tx * 4 + j;
                    float d = 0.f;
#pragma unroll
                    for (int c = 0; c < NC; c++)
                        d = __fmaf_rn(sx[rb][c], sWin[cj][c], d);
                    const int q = i * 4 + j;
                    float vn = __fadd_rn(__fmaf_rn(ALPHA, v[q], d), acc[i][j]);
                    float s = (vn >= 1.0f) ? 1.0f : 0.0f;
                    v[q] = (vn >= 1.0f) ? 0.0f : vn;
                    cnt[q] += s;
                    sp[j] = s;
                    spt[cj][rb] = s;
                }
                __stcg((float4*)&s_next[(size_t)(b0 + rb) * NRES + j0 + tx * 4],
                       make_float4(sp[0], sp[1], sp[2], sp[3]));
            }
            __syncthreads();
            // Coalesced transposed spike store.
            for (int e = tid; e < 64 * 16; e += 256) {
                int jl = e >> 4, bq = e & 15;
                float4 val = *(const float4*)&spt[jl][bq * 4];
                __stcg((float4*)&sT_next[(size_t)(j0 + jl) * NB + b0 + bq * 4], val);
            }

            grid_barrier();
        }
        grid_barrier();   // classifier finishes step NT-1

#pragma unroll
        for (int i = 0; i < 4; i++) {
            *(float4*)&out[(size_t)NB * NCLS +
                           (size_t)(b0 + ty * 4 + i) * NRES + j0 + tx * 4] =
                make_float4(cnt[i * 4 + 0], cnt[i * 4 + 1], cnt[i * 4 + 2], cnt[i * 4 + 3]);
        }
    } else {
        // ---------------- Classifier path (numerics unchanged) ----------------
        const int idx = (blk - 128) * 256 + tid;   // 0..5119
        const int b = idx / NCLS;
        const int m = idx % NCLS;
        float vc = 0.f, cc = 0.f;

        grid_barrier();

        for (int t = 0; t <= NT; ++t) {
            if (t >= 1) {
                const float* __restrict__ s_prev = g_s[t & 1];  // spikes of step t-1
                const float* srow = &s_prev[(size_t)b * NRES];
                const float* wrow = &Wclf[(size_t)m * NRES];
                float tot = 0.f;
#pragma unroll
                for (int blkk = 0; blkk < 4; ++blkk) {
                    float a = 0.f;
#pragma unroll 8
                    for (int n = 0; n < 256; n += 4) {
                        int base = blkk * 256 + n;
                        float4 sv = __ldcg((const float4*)(srow + base));
                        float4 wv = *(const float4*)(wrow + base);
                        a = __fmaf_rn(sv.x, wv.x, a);
                        a = __fmaf_rn(sv.y, wv.y, a);
                        a = __fmaf_rn(sv.z, wv.z, a);
                        a = __fmaf_rn(sv.w, wv.w, a);
                    }
                    tot = __fadd_rn(tot, a);
                }
                float vn = __fmaf_rn(ALPHA, vc, tot);
                float s = (vn >= 1.0f) ? 1.0f : 0.0f;
                vc = (vn >= 1.0f) ? 0.0f : vn;
                cc += s;
            }
            grid_barrier();
        }
        out[idx] = cc;
    }
}

extern "C" void kernel_launch(void* const* d_in, const int* in_sizes, int n_in,
                              void* d_out, int out_size) {
    const float* x = 0; const float* Win = 0;
    const float* Wres = 0; const float* Wclf = 0;
    for (int i = 0; i < n_in; ++i) {
        switch (in_sizes[i]) {
            case NB * NC * NT:   x    = (const float*)d_in[i]; break;
            case NRES * NC:      Win  = (const float*)d_in[i]; break;
            case NRES * NRES:    Wres = (const float*)d_in[i]; break;
            case NCLS * NRES:    Wclf = (const float*)d_in[i]; break;
        }
    }
    float* out = (float*)d_out;

    reservoir_persistent<<<NBLK, 256>>>(x, Win, Wres, Wclf, out);
}

// round 10
// speedup vs baseline: 1.0151x; 1.0151x over previous
#include <cuda_runtime.h>

#define NB   512
#define NC   16
#define NT   2000
#define NRES 1024
#define NCLS 10
#define NBLK 148
#define ALPHA 0.9f

// Persistent cross-CTA state.
__device__ float g_s [2][NB * NRES];   // spikes, [b][j] (classifier layout)
__device__ float g_sT[2][NRES * NB];   // spikes, [k][b] (GEMM A layout)
__device__ float g_WresT[NRES * NRES]; // Wres^T, [k][j]
__device__ float g_xT[(size_t)NT * NB * NC];  // x^T: [t][b][c]
__device__ unsigned g_bar_count;
__device__ unsigned g_bar_gen;

static __device__ __forceinline__ unsigned ld_acq(const unsigned* p) {
    unsigned v;
    asm volatile("ld.acquire.gpu.global.u32 %0, [%1];" : "=r"(v) : "l"(p) : "memory");
    return v;
}
static __device__ __forceinline__ void st_rel(unsigned* p, unsigned v) {
    asm volatile("st.release.gpu.global.u32 [%0], %1;" :: "l"(p), "r"(v) : "memory");
}

// Grid-wide barrier; all 148 CTAs resident (1 per SM).
static __device__ __forceinline__ void grid_barrier() {
    __syncthreads();
    if (threadIdx.x == 0) {
        unsigned gen = ld_acq(&g_bar_gen);
        __threadfence();
        if (atomicAdd(&g_bar_count, 1u) == NBLK - 1u) {
            g_bar_count = 0u;
            __threadfence();
            st_rel(&g_bar_gen, gen + 1u);
        } else {
            while (ld_acq(&g_bar_gen) == gen) { }
        }
    }
    __syncthreads();
}

// fma.rn.f32x2: two independent rn fp32 FMAs — per-lane bit-identical.
static __device__ __forceinline__ unsigned long long pack2(float lo, float hi) {
    unsigned long long r;
    asm("mov.b64 %0, {%1, %2};" : "=l"(r) : "f"(lo), "f"(hi));
    return r;
}
static __device__ __forceinline__ void unpack2(unsigned long long p, float& lo, float& hi) {
    asm("mov.b64 {%0, %1}, %2;" : "=f"(lo), "=f"(hi) : "l"(p));
}
static __device__ __forceinline__ void fma2(unsigned long long& acc,
                                            unsigned long long a,
                                            unsigned long long b) {
    asm("fma.rn.f32x2 %0, %1, %2, %0;" : "+l"(acc) : "l"(a), "l"(b));
}

__global__ __launch_bounds__(256, 1) void reservoir_persistent(
    const float* __restrict__ x,     // (NB, NC, NT)
    const float* __restrict__ Win,   // (NRES, NC)
    const float* __restrict__ Wres,  // (NRES, NRES)
    const float* __restrict__ Wclf,  // (NCLS, NRES)
    float* __restrict__ out)         // [NB*NCLS | NB*NRES]
{
    const int blk = blockIdx.x;
    const int tid = threadIdx.x;

    // Pool: As rows 0..31, Bs rows 32..63 (each [32][68]);
    // aliased as spt[64][68] in the epilogue.
    __shared__ __align__(16) float pool[64 * 68];
    __shared__ float sx[64][17];
    __shared__ float sWin[64][17];
    float* const As = pool;             // As[k][b_local]: k*68 + bl
    float* const Bs = pool + 32 * 68;   // Bs[k][j_local]: k*68 + jl

    // ---- Phase 0 (all CTAs): one-time transposes ----
    {
        const int g0 = blk * 256 + tid;
        const int gs = NBLK * 256;
        for (int i = g0; i < NRES * NRES; i += gs) {
            int j = i >> 10, k = i & (NRES - 1);
            g_WresT[k * NRES + j] = Wres[i];
        }
        for (size_t i = g0; i < (size_t)NT * NB * NC; i += (size_t)gs) {
            int t = (int)(i >> 13);           // NB*NC = 8192
            int r = (int)(i & 8191);
            int b = r >> 4, c = r & 15;
            g_xT[i] = x[((size_t)(b * NC + c)) * NT + t];
        }
    }

    if (blk < 128) {
        // ---------------- Reservoir path ----------------
        const int b0 = (blk >> 4) * 64;
        const int j0 = (blk & 15) * 64;

        // Mainloop decode: warp = 16b x 32j, lane = 4b x 4j.
        const int w    = tid >> 5;
        const int lane = tid & 31;
        const int Q = w >> 1;            // b-quarter 0..3  (16 b each)
        const int H = w & 1;             // j-half    0..1  (32 j each)
        const int bgrp = lane >> 3;      // 0..3 (4 b each)
        const int jgrp = lane & 7;       // 0..7 (4 j each)
        const int rl0 = Q * 16 + bgrp * 4;   // CTA-local first row
        const int cl0 = H * 32 + jgrp * 4;   // CTA-local first col

        // Staging decode (coalesced, conflict-free).
        const int kl0 = tid >> 4;        // 0..15
        const int qq  = tid & 15;        // 0..15

        // Zero step-0 spikes (both layouts).
        {
            float4 z = make_float4(0.f, 0.f, 0.f, 0.f);
#pragma unroll
            for (int i = 0; i < 4; i++)
                __stcg((float4*)&g_s[0][(size_t)(b0 + rl0 + i) * NRES + j0 + cl0], z);
            for (int e = tid; e < 64 * 16; e += 256) {
                int jl = e >> 4, bq = e & 15;
                __stcg((float4*)&g_sT[0][(size_t)(j0 + jl) * NB + b0 + bq * 4], z);
            }
        }
        for (int e = tid; e < 64 * 16; e += 256) {
            int r = e >> 4, c = e & 15;
            sWin[r][c] = Win[(size_t)(j0 + r) * NC + c];
        }

        float v[16], cnt[16];
#pragma unroll
        for (int q = 0; q < 16; q++) { v[q] = 0.f; cnt[q] = 0.f; }

        grid_barrier();

        for (int t = 0; t < NT; ++t) {
            const float* __restrict__ sTprev = g_sT[t & 1];
            float* __restrict__ s_next  = g_s [(t + 1) & 1];
            float* __restrict__ sT_next = g_sT[(t + 1) & 1];

            // Stage x_t tile, coalesced from g_xT.
            {
                const float* xt = &g_xT[(size_t)t * (NB * NC) + (size_t)b0 * NC];
                for (int e = tid; e < 64 * 16; e += 256)
                    sx[e >> 4][e & 15] = xt[e];
            }

            // Frozen chain: per output a single accumulator, k strictly
            // descending 1023..0; FFMA2 j-pairing identical to rounds 8/9.
            unsigned long long acc2[4][2];
#pragma unroll
            for (int i = 0; i < 4; i++) {
                acc2[i][0] = pack2(0.f, 0.f);
                acc2[i][1] = pack2(0.f, 0.f);
            }

            // Prefetch chunk 31 (k = 992..1023), fully coalesced.
            float4 pa0, pa1, pb0, pb1;
            {
                const int kg = 31 * 32;
                pa0 = __ldcg((const float4*)&sTprev[(size_t)(kg + kl0)      * NB + b0 + qq * 4]);
                pa1 = __ldcg((const float4*)&sTprev[(size_t)(kg + kl0 + 16) * NB + b0 + qq * 4]);
                pb0 = __ldg ((const float4*)&g_WresT[(size_t)(kg + kl0)      * NRES + j0 + qq * 4]);
                pb1 = __ldg ((const float4*)&g_WresT[(size_t)(kg + kl0 + 16) * NRES + j0 + qq * 4]);
            }

            for (int kc = 31; kc >= 0; --kc) {
                __syncthreads();   // prior compute done before overwrite
                *(float4*)&As[(kl0)      * 68 + qq * 4] = pa0;
                *(float4*)&As[(kl0 + 16) * 68 + qq * 4] = pa1;
                *(float4*)&Bs[(kl0)      * 68 + qq * 4] = pb0;
                *(float4*)&Bs[(kl0 + 16) * 68 + qq * 4] = pb1;
                __syncthreads();
                if (kc > 0) {
                    const int kg = (kc - 1) * 32;
                    pa0 = __ldcg((const float4*)&sTprev[(size_t)(kg + kl0)      * NB + b0 + qq * 4]);
                    pa1 = __ldcg((const float4*)&sTprev[(size_t)(kg + kl0 + 16) * NB + b0 + qq * 4]);
                    pb0 = __ldg ((const float4*)&g_WresT[(size_t)(kg + kl0)      * NRES + j0 + qq * 4]);
                    pb1 = __ldg ((const float4*)&g_WresT[(size_t)(kg + kl0 + 16) * NRES + j0 + qq * 4]);
                }
#pragma unroll
                for (int k = 31; k >= 0; --k) {
                    // One LDS.128 each, <=128B unique, conflict-free.
                    float4 a4 = *(const float4*)&As[k * 68 + rl0];
                    float4 b4 = *(const float4*)&Bs[k * 68 + cl0];
                    unsigned long long b01 = pack2(b4.x, b4.y);
                    unsigned long long b23 = pack2(b4.z, b4.w);
                    float aa[4] = {a4.x, a4.y, a4.z, a4.w};
#pragma unroll
                    for (int i = 0; i < 4; i++) {
                        unsigned long long ai2 = pack2(aa[i], aa[i]);
                        fma2(acc2[i][0], ai2, b01);
                        fma2(acc2[i][1], ai2, b23);
                    }
                }
            }

            float acc[4][4];
#pragma unroll
            for (int i = 0; i < 4; i++) {
                unpack2(acc2[i][0], acc[i][0], acc[i][1]);
                unpack2(acc2[i][1], acc[i][2], acc[i][3]);
            }

            __syncthreads();   // mainloop smem reads done; pool reused as spt

            // Epilogue (frozen): vn = rn(fma(0.9, v, d_in) + d_rec)
            float (*spt)[68] = (float(*)[68])pool;   // [j_local][b_local]
#pragma unroll
            for (int i = 0; i < 4; i++) {
                const int rb = rl0 + i;
                float sp[4];
#pragma unroll
                for (int j = 0; j < 4; j++) {
                    const int cj = cl0 + j;
                    float d = 0.f;
#pragma unroll
                    for (int c = 0; c < NC; c++)
                        d = __fmaf_rn(sx[rb][c], sWin[cj][c], d);
                    const int q = i * 4 + j;
                    float vn = __fadd_rn(__fmaf_rn(ALPHA, v[q], d), acc[i][j]);
                    float s = (vn >= 1.0f) ? 1.0f : 0.0f;
                    v[q] = (vn >= 1.0f) ? 0.0f : vn;
                    cnt[q] += s;
                    sp[j] = s;
                    spt[cj][rb] = s;
                }
                __stcg((float4*)&s_next[(size_t)(b0 + rb) * NRES + j0 + cl0],
                       make_float4(sp[0], sp[1], sp[2], sp[3]));
            }
            __syncthreads();
            // Coalesced transposed spike store.
            for (int e = tid; e < 64 * 16; e += 256) {
                int jl = e >> 4, bq = e & 15;
                float4 val = *(const float4*)&spt[jl][bq * 4];
                __stcg((float4*)&sT_next[(size_t)(j0 + jl) * NB + b0 + bq * 4], val);
            }

            grid_barrier();
        }
        grid_barrier();   // classifier finishes step NT-1

#pragma unroll
        for (int i = 0; i < 4; i++) {
            *(float4*)&out[(size_t)NB * NCLS +
                           (size_t)(b0 + rl0 + i) * NRES + j0 + cl0] =
                make_float4(cnt[i * 4 + 0], cnt[i * 4 + 1], cnt[i * 4 + 2], cnt[i * 4 + 3]);
        }
    } else {
        // ---------------- Classifier path (numerics unchanged) ----------------
        const int idx = (blk - 128) * 256 + tid;   // 0..5119
        const int b = idx / NCLS;
        const int m = idx % NCLS;
        float vc = 0.f, cc = 0.f;

        grid_barrier();

        for (int t = 0; t <= NT; ++t) {
            if (t >= 1) {
                const float* __restrict__ s_prev = g_s[t & 1];  // spikes of step t-1
                const float* srow = &s_prev[(size_t)b * NRES];
                const float* wrow = &Wclf[(size_t)m * NRES];
                float tot = 0.f;
#pragma unroll
                for (int blkk = 0; blkk < 4; ++blkk) {
                    float a = 0.f;
#pragma unroll 8
                    for (int n = 0; n < 256; n += 4) {
                        int base = blkk * 256 + n;
                        float4 sv = __ldcg((const float4*)(srow + base));
                        float4 wv = *(const float4*)(wrow + base);
                        a = __fmaf_rn(sv.x, wv.x, a);
                        a = __fmaf_rn(sv.y, wv.y, a);
                        a = __fmaf_rn(sv.z, wv.z, a);
                        a = __fmaf_rn(sv.w, wv.w, a);
                    }
                    tot = __fadd_rn(tot, a);
                }
                float vn = __fmaf_rn(ALPHA, vc, tot);
                float s = (vn >= 1.0f) ? 1.0f : 0.0f;
                vc = (vn >= 1.0f) ? 0.0f : vn;
                cc += s;
            }
            grid_barrier();
        }
        out[idx] = cc;
    }
}

extern "C" void kernel_launch(void* const* d_in, const int* in_sizes, int n_in,
                              void* d_out, int out_size) {
    const float* x = 0; const float* Win = 0;
    const float* Wres = 0; const float* Wclf = 0;
    for (int i = 0; i < n_in; ++i) {
        switch (in_sizes[i]) {
            case NB * NC * NT:   x    = (const float*)d_in[i]; break;
            case NRES * NC:      Win  = (const float*)d_in[i]; break;
            case NRES * NRES:    Wres = (const float*)d_in[i]; break;
            case NCLS * NRES:    Wclf = (const float*)d_in[i]; break;
        }
    }
    float* out = (float*)d_out;

    reservoir_persistent<<<NBLK, 256>>>(x, Win, Wres, Wclf, out);
}

// round 11
// speedup vs baseline: 1.0664x; 1.0506x over previous
#include <cuda_runtime.h>

#define NB   512
#define NC   16
#define NT   2000
#define NRES 1024
#define NCLS 10
#define NBLK 148
#define ALPHA 0.9f

// Persistent cross-CTA state.
__device__ float g_s [2][NB * NRES];   // spikes, [b][j] (classifier layout)
__device__ float g_sT[2][NRES * NB];   // spikes, [k][b] (GEMM A layout)
__device__ float g_WresT[NRES * NRES]; // Wres^T, [k][j]
__device__ float g_xT[(size_t)NT * NB * NC];  // x^T: [t][b][c]
__device__ unsigned g_bar_count;
__device__ unsigned g_bar_gen;

static __device__ __forceinline__ unsigned ld_acq(const unsigned* p) {
    unsigned v;
    asm volatile("ld.acquire.gpu.global.u32 %0, [%1];" : "=r"(v) : "l"(p) : "memory");
    return v;
}
static __device__ __forceinline__ void st_rel(unsigned* p, unsigned v) {
    asm volatile("st.release.gpu.global.u32 [%0], %1;" :: "l"(p), "r"(v) : "memory");
}

// Grid-wide barrier; all 148 CTAs resident (1 per SM).
static __device__ __forceinline__ void grid_barrier() {
    __syncthreads();
    if (threadIdx.x == 0) {
        unsigned gen = ld_acq(&g_bar_gen);
        __threadfence();
        if (atomicAdd(&g_bar_count, 1u) == NBLK - 1u) {
            g_bar_count = 0u;
            __threadfence();
            st_rel(&g_bar_gen, gen + 1u);
        } else {
            while (ld_acq(&g_bar_gen) == gen) { }
        }
    }
    __syncthreads();
}

// fma.rn.f32x2: two independent rn fp32 FMAs — per-lane bit-identical.
static __device__ __forceinline__ unsigned long long pack2(float lo, float hi) {
    unsigned long long r;
    asm("mov.b64 %0, {%1, %2};" : "=l"(r) : "f"(lo), "f"(hi));
    return r;
}
static __device__ __forceinline__ void unpack2(unsigned long long p, float& lo, float& hi) {
    asm("mov.b64 {%0, %1}, %2;" : "=f"(lo), "=f"(hi) : "l"(p));
}
static __device__ __forceinline__ void fma2(unsigned long long& acc,
                                            unsigned long long a,
                                            unsigned long long b) {
    asm("fma.rn.f32x2 %0, %1, %2, %0;" : "+l"(acc) : "l"(a), "l"(b));
}

// cp.async 16B global->shared (cache-global), commit/wait.
static __device__ __forceinline__ void cp16(unsigned dst_smem, const void* src) {
    asm volatile("cp.async.cg.shared.global [%0], [%1], 16;"
                 :: "r"(dst_smem), "l"(src) : "memory");
}
static __device__ __forceinline__ void cp_commit() {
    asm volatile("cp.async.commit_group;" ::: "memory");
}
static __device__ __forceinline__ void cp_wait0() {
    asm volatile("cp.async.wait_group 0;" ::: "memory");
}

__global__ __launch_bounds__(256, 1) void reservoir_persistent(
    const float* __restrict__ x,     // (NB, NC, NT)
    const float* __restrict__ Win,   // (NRES, NC)
    const float* __restrict__ Wres,  // (NRES, NRES)
    const float* __restrict__ Wclf,  // (NCLS, NRES)
    float* __restrict__ out)         // [NB*NCLS | NB*NRES]
{
    const int blk = blockIdx.x;
    const int tid = threadIdx.x;

    // Double-buffered staging pool: buf{0,1} x (As[32][68], Bs[32][68]).
    // Epilogue aliases the first 64x68 floats as spt.
    __shared__ __align__(16) float pool[2 * 64 * 68];
    __shared__ float sx[64][17];
    __shared__ float sWin[64][17];

    // ---- Phase 0 (all CTAs): one-time transposes ----
    {
        const int g0 = blk * 256 + tid;
        const int gs = NBLK * 256;
        for (int i = g0; i < NRES * NRES; i += gs) {
            int j = i >> 10, k = i & (NRES - 1);
            g_WresT[k * NRES + j] = Wres[i];
        }
        for (size_t i = g0; i < (size_t)NT * NB * NC; i += (size_t)gs) {
            int t = (int)(i >> 13);           // NB*NC = 8192
            int r = (int)(i & 8191);
            int b = r >> 4, c = r & 15;
            g_xT[i] = x[((size_t)(b * NC + c)) * NT + t];
        }
    }

    if (blk < 128) {
        // ---------------- Reservoir path ----------------
        const int b0 = (blk >> 4) * 64;
        const int j0 = (blk & 15) * 64;

        // Mainloop decode (r10 tiling): warp = 16b x 32j, lane = 4b x 4j.
        const int w    = tid >> 5;
        const int lane = tid & 31;
        const int Q = w >> 1;                // b-quarter
        const int H = w & 1;                 // j-half
        const int rl0 = Q * 16 + (lane >> 3) * 4;
        const int cl0 = H * 32 + (lane & 7) * 4;

        // Staging decode.
        const int kl0 = tid >> 4;            // 0..15
        const int qq  = tid & 15;            // 0..15

        // Smem byte addresses for this thread's 4 cp.async destinations.
        const unsigned pool_base = (unsigned)__cvta_generic_to_shared(pool);
        const unsigned bufBytes = 64 * 68 * 4;
        const unsigned dA0 = pool_base + ((kl0)      * 68 + qq * 4) * 4;
        const unsigned dA1 = pool_base + ((kl0 + 16) * 68 + qq * 4) * 4;
        const unsigned dB0 = pool_base + ((32 + kl0)      * 68 + qq * 4) * 4;
        const unsigned dB1 = pool_base + ((32 + kl0 + 16) * 68 + qq * 4) * 4;

        // Zero step-0 spikes (both layouts).
        {
            float4 z = make_float4(0.f, 0.f, 0.f, 0.f);
#pragma unroll
            for (int i = 0; i < 4; i++)
                __stcg((float4*)&g_s[0][(size_t)(b0 + rl0 + i) * NRES + j0 + cl0], z);
            for (int e = tid; e < 64 * 16; e += 256) {
                int jl = e >> 4, bq = e & 15;
                __stcg((float4*)&g_sT[0][(size_t)(j0 + jl) * NB + b0 + bq * 4], z);
            }
        }
        for (int e = tid; e < 64 * 16; e += 256) {
            int r = e >> 4, c = e & 15;
            sWin[r][c] = Win[(size_t)(j0 + r) * NC + c];
        }

        float v[16], cnt[16];
#pragma unroll
        for (int q = 0; q < 16; q++) { v[q] = 0.f; cnt[q] = 0.f; }

        grid_barrier();

        for (int t = 0; t < NT; ++t) {
            const float* __restrict__ sTprev = g_sT[t & 1];
            float* __restrict__ s_next  = g_s [(t + 1) & 1];
            float* __restrict__ sT_next = g_sT[(t + 1) & 1];

            // Stage x_t tile (coalesced; consumed in epilogue after syncs).
            {
                const float* xt = &g_xT[(size_t)t * (NB * NC) + (size_t)b0 * NC];
                for (int e = tid; e < 64 * 16; e += 256)
                    sx[e >> 4][e & 15] = xt[e];
            }

            unsigned long long acc2[4][2];
#pragma unroll
            for (int i = 0; i < 4; i++) {
                acc2[i][0] = pack2(0.f, 0.f);
                acc2[i][1] = pack2(0.f, 0.f);
            }

            // Prologue: async-stage chunk 31 into buf (31&1)=1.
            {
                const int kg = 31 * 32;
                const unsigned off = bufBytes;   // buf 1
                cp16(dA0 + off, &sTprev [(size_t)(kg + kl0)      * NB   + b0 + qq * 4]);
                cp16(dA1 + off, &sTprev [(size_t)(kg + kl0 + 16) * NB   + b0 + qq * 4]);
                cp16(dB0 + off, &g_WresT[(size_t)(kg + kl0)      * NRES + j0 + qq * 4]);
                cp16(dB1 + off, &g_WresT[(size_t)(kg + kl0 + 16) * NRES + j0 + qq * 4]);
                cp_commit();
            }

            for (int kc = 31; kc >= 0; --kc) {
                cp_wait0();        // chunk kc landed in buf[kc&1]
                __syncthreads();   // visible to all; prior compute done

                if (kc > 0) {      // async-stage chunk kc-1 (overlaps compute)
                    const int kg = (kc - 1) * 32;
                    const unsigned off = ((kc - 1) & 1) * bufBytes;
                    cp16(dA0 + off, &sTprev [(size_t)(kg + kl0)      * NB   + b0 + qq * 4]);
                    cp16(dA1 + off, &sTprev [(size_t)(kg + kl0 + 16) * NB   + b0 + qq * 4]);
                    cp16(dB0 + off, &g_WresT[(size_t)(kg + kl0)      * NRES + j0 + qq * 4]);
                    cp16(dB1 + off, &g_WresT[(size_t)(kg + kl0 + 16) * NRES + j0 + qq * 4]);
                    cp_commit();
                }

                const float* As = pool + (kc & 1) * (64 * 68);
                const float* Bs = As + 32 * 68;
#pragma unroll
                for (int k = 31; k >= 0; --k) {
                    float4 a4 = *(const float4*)&As[k * 68 + rl0];
                    float4 b4 = *(const float4*)&Bs[k * 68 + cl0];
                    unsigned long long b01 = pack2(b4.x, b4.y);
                    unsigned long long b23 = pack2(b4.z, b4.w);
                    float aa[4] = {a4.x, a4.y, a4.z, a4.w};
#pragma unroll
                    for (int i = 0; i < 4; i++) {
                        unsigned long long ai2 = pack2(aa[i], aa[i]);
                        fma2(acc2[i][0], ai2, b01);
                        fma2(acc2[i][1], ai2, b23);
                    }
                }
            }

            float acc[4][4];
#pragma unroll
            for (int i = 0; i < 4; i++) {
                unpack2(acc2[i][0], acc[i][0], acc[i][1]);
                unpack2(acc2[i][1], acc[i][2], acc[i][3]);
            }

            __syncthreads();   // mainloop reads done; pool reused as spt

            // Epilogue (frozen): vn = rn(fma(0.9, v, d_in) + d_rec)
            float (*spt)[68] = (float(*)[68])pool;   // [j_local][b_local]
#pragma unroll
            for (int i = 0; i < 4; i++) {
                const int rb = rl0 + i;
                float sp[4];
#pragma unroll
                for (int j = 0; j < 4; j++) {
                    const int cj = cl0 + j;
                    float d = 0.f;
#pragma unroll
                    for (int c = 0; c < NC; c++)
                        d = __fmaf_rn(sx[rb][c], sWin[cj][c], d);
                    const int q = i * 4 + j;
                    float vn = __fadd_rn(__fmaf_rn(ALPHA, v[q], d), acc[i][j]);
                    float s = (vn >= 1.0f) ? 1.0f : 0.0f;
                    v[q] = (vn >= 1.0f) ? 0.0f : vn;
                    cnt[q] += s;
                    sp[j] = s;
                    spt[cj][rb] = s;
                }
                __stcg((float4*)&s_next[(size_t)(b0 + rb) * NRES + j0 + cl0],
                       make_float4(sp[0], sp[1], sp[2], sp[3]));
            }
            __syncthreads();
            for (int e = tid; e < 64 * 16; e += 256) {
                int jl = e >> 4, bq = e & 15;
                float4 val = *(const float4*)&spt[jl][bq * 4];
                __stcg((float4*)&sT_next[(size_t)(j0 + jl) * NB + b0 + bq * 4], val);
            }

            grid_barrier();
        }
        grid_barrier();   // classifier finishes step NT-1

#pragma unroll
        for (int i = 0; i < 4; i++) {
            *(float4*)&out[(size_t)NB * NCLS +
                           (size_t)(b0 + rl0 + i) * NRES + j0 + cl0] =
                make_float4(cnt[i * 4 + 0], cnt[i * 4 + 1], cnt[i * 4 + 2], cnt[i * 4 + 3]);
        }
    } else {
        // ---------------- Classifier path (numerics unchanged) ----------------
        const int idx = (blk - 128) * 256 + tid;   // 0..5119
        const int b = idx / NCLS;
        const int m = idx % NCLS;
        float vc = 0.f, cc = 0.f;

        grid_barrier();

        for (int t = 0; t <= NT; ++t) {
            if (t >= 1) {
                const float* __restrict__ s_prev = g_s[t & 1];  // spikes of step t-1
                const float* srow = &s_prev[(size_t)b * NRES];
                const float* wrow = &Wclf[(size_t)m * NRES];
                float tot = 0.f;
#pragma unroll
                for (int blkk = 0; blkk < 4; ++blkk) {
                    float a = 0.f;
#pragma unroll 8
                    for (int n = 0; n < 256; n += 4) {
                        int base = blkk * 256 + n;
                        float4 sv = __ldcg((const float4*)(srow + base));
                        float4 wv = *(const float4*)(wrow + base);
                        a = __fmaf_rn(sv.x, wv.x, a);
                        a = __fmaf_rn(sv.y, wv.y, a);
                        a = __fmaf_rn(sv.z, wv.z, a);
                        a = __fmaf_rn(sv.w, wv.w, a);
                    }
                    tot = __fadd_rn(tot, a);
                }
                float vn = __fmaf_rn(ALPHA, vc, tot);
                float s = (vn >= 1.0f) ? 1.0f : 0.0f;
                vc = (vn >= 1.0f) ? 0.0f : vn;
                cc += s;
            }
            grid_barrier();
        }
        out[idx] = cc;
    }
}

extern "C" void kernel_launch(void* const* d_in, const int* in_sizes, int n_in,
                              void* d_out, int out_size) {
    const float* x = 0; const float* Win = 0;
    const float* Wres = 0; const float* Wclf = 0;
    for (int i = 0; i < n_in; ++i) {
        switch (in_sizes[i]) {
            case NB * NC * NT:   x    = (const float*)d_in[i]; break;
            case NRES * NC:      Win  = (const float*)d_in[i]; break;
            case NRES * NRES:    Wres = (const float*)d_in[i]; break;
            case NCLS * NRES:    Wclf = (const float*)d_in[i]; break;
        }
    }
    float* out = (float*)d_out;

    reservoir_persistent<<<NBLK, 256>>>(x, Win, Wres, Wclf, out);
}